// round 16
// baseline (speedup 1.0000x reference)
#include <cuda_runtime.h>
#include <cstdint>
#include <math.h>

// ---------------------------------------------------------------- constants
#define BATCH 4096
#define NROWS 8192
#define DIM   256

#define LN2f  0.69314718055994531f
#define C2    2.8853900817779268f            // 2*log2(e)  (1/T * log2 e, T=0.5)
#define SCALE 1.6986442f                     // sqrt(2*log2 e)

#define BM 128                                // rows per stripe
#define BN 64                                 // cols per tile job
#define TT2     4160                          // triangle jobs: sum_i (128-2i)
#define GRID    296                           // 2 CTAs per SM, exactly

#define PITCH   272                           // smem row pitch (256B data + 16B pad)
#define A_BYTES (BM * PITCH)                  // 34816
#define B_BYTES (BN * PITCH)                  // 17408
#define SMEM_A  0
#define SMEM_B0 A_BYTES
#define SMEM_B1 (A_BYTES + B_BYTES)
#define SMEM_TOTAL (A_BYTES + 2 * B_BYTES)    // 69632 -> 2 CTAs/SM

// ------------------------------------------------------------ device scratch
__device__ __align__(16) uint32_t g_q[NROWS * 64];   // e4m3 rows (64 u32 = 256B)
__device__ float g_s[NROWS];                         // per-row exp2 sums (atomic)
__device__ float g_diag[NROWS];                      // exact fp8 self-logit (log2)
__device__ float g_pos[NROWS];                       // fp32 positive logit (log2)
__device__ unsigned g_cnt;

// ------------------------------------------------------------- asm helpers
__device__ __forceinline__ uint32_t smem_u32(const void* p) {
    uint32_t a;
    asm("{ .reg .u64 t; cvta.to.shared.u64 t, %1; cvt.u32.u64 %0, t; }" : "=r"(a) : "l"(p));
    return a;
}
__device__ __forceinline__ float ex2f(float x) {
    float y; asm("ex2.approx.ftz.f32 %0, %1;" : "=f"(y) : "f"(x)); return y;
}
__device__ __forceinline__ float lg2f(float x) {
    float y; asm("lg2.approx.f32 %0, %1;" : "=f"(y) : "f"(x)); return y;
}
__device__ __forceinline__ float ldcg(const float* p) {
    float v; asm volatile("ld.global.cg.f32 %0, [%1];" : "=f"(v) : "l"(p)); return v;
}
__device__ __forceinline__ void cp16(uint32_t s, const void* g) {
    asm volatile("cp.async.cg.shared.global [%0], [%1], 16;" :: "r"(s), "l"(g));
}
__device__ __forceinline__ void cp_commit() { asm volatile("cp.async.commit_group;"); }
__device__ __forceinline__ void cp_wait0()  { asm volatile("cp.async.wait_group 0;" ::: "memory"); }
__device__ __forceinline__ void ldmx4(uint32_t* r, uint32_t addr) {
    asm volatile("ldmatrix.sync.aligned.m8n8.x4.shared.b16 {%0,%1,%2,%3}, [%4];"
                 : "=r"(r[0]), "=r"(r[1]), "=r"(r[2]), "=r"(r[3]) : "r"(addr));
}
__device__ __forceinline__ void mma_fp8(float* c, const uint32_t* a,
                                        uint32_t b0, uint32_t b1) {
    asm volatile("mma.sync.aligned.m16n8k32.row.col.f32.e4m3.e4m3.f32 "
                 "{%0,%1,%2,%3}, {%4,%5,%6,%7}, {%8,%9}, {%0,%1,%2,%3};"
                 : "+f"(c[0]), "+f"(c[1]), "+f"(c[2]), "+f"(c[3])
                 : "r"(a[0]), "r"(a[1]), "r"(a[2]), "r"(a[3]), "r"(b0), "r"(b1));
}
__device__ __forceinline__ uint32_t fp8pack4(float x, float y, float z, float w) {
    uint16_t lo, hi; uint32_t r;
    asm("cvt.rn.satfinite.e4m3x2.f32 %0, %2, %1;" : "=h"(lo) : "f"(x), "f"(y));
    asm("cvt.rn.satfinite.e4m3x2.f32 %0, %2, %1;" : "=h"(hi) : "f"(z), "f"(w));
    asm("mov.b32 %0, {%1, %2};" : "=r"(r) : "h"(lo), "h"(hi));
    return r;
}
__device__ __forceinline__ float fp8_sq4(uint32_t v) {
    float f0, f1, f2, f3;
    asm("{ .reg .b16 l, h, a, b, c, d;\n\t"
        "  mov.b32 {l, h}, %4;\n\t"
        "  .reg .b32 p, q;\n\t"
        "  cvt.rn.f16x2.e4m3x2 p, l;\n\t"
        "  cvt.rn.f16x2.e4m3x2 q, h;\n\t"
        "  mov.b32 {a, b}, p;\n\t"
        "  mov.b32 {c, d}, q;\n\t"
        "  cvt.f32.f16 %0, a;\n\t"
        "  cvt.f32.f16 %1, b;\n\t"
        "  cvt.f32.f16 %2, c;\n\t"
        "  cvt.f32.f16 %3, d; }"
        : "=f"(f0), "=f"(f1), "=f"(f2), "=f"(f3) : "r"(v));
    return f0*f0 + f1*f1 + f2*f2 + f3*f3;
}

// ---------------------------------------------------------------------------
// Kernel 1 (prep): one warp per pair (r, r+B). Resets g_s / g_cnt.
// ---------------------------------------------------------------------------
__global__ __launch_bounds__(256) void k_prep(const float* __restrict__ ei,
                                              const float* __restrict__ ej)
{
    int w = threadIdx.x >> 5, lane = threadIdx.x & 31;
    int r = blockIdx.x * 8 + w;

    int gid = blockIdx.x * 256 + threadIdx.x;
    if (gid < NROWS) g_s[gid] = 0.f;
    if (gid == 0) g_cnt = 0;

    const float4* A4 = (const float4*)(ei + (size_t)r * DIM);
    const float4* B4 = (const float4*)(ej + (size_t)r * DIM);
    float4 a0 = A4[lane], a1 = A4[lane + 32];
    float4 b0 = B4[lane], b1 = B4[lane + 32];

    float na = a0.x*a0.x + a0.y*a0.y + a0.z*a0.z + a0.w*a0.w
             + a1.x*a1.x + a1.y*a1.y + a1.z*a1.z + a1.w*a1.w;
    float nb = b0.x*b0.x + b0.y*b0.y + b0.z*b0.z + b0.w*b0.w
             + b1.x*b1.x + b1.y*b1.y + b1.z*b1.z + b1.w*b1.w;
    float ab = a0.x*b0.x + a0.y*b0.y + a0.z*b0.z + a0.w*b0.w
             + a1.x*b1.x + a1.y*b1.y + a1.z*b1.z + a1.w*b1.w;
    #pragma unroll
    for (int o = 16; o > 0; o >>= 1) {
        na += __shfl_xor_sync(0xFFFFFFFFu, na, o);
        nb += __shfl_xor_sync(0xFFFFFFFFu, nb, o);
        ab += __shfl_xor_sync(0xFFFFFFFFu, ab, o);
    }
    float inva = rsqrtf(na) * SCALE;
    float invb = rsqrtf(nb) * SCALE;

    uint32_t qa0 = fp8pack4(a0.x*inva, a0.y*inva, a0.z*inva, a0.w*inva);
    uint32_t qa1 = fp8pack4(a1.x*inva, a1.y*inva, a1.z*inva, a1.w*inva);
    uint32_t qb0 = fp8pack4(b0.x*invb, b0.y*invb, b0.z*invb, b0.w*invb);
    uint32_t qb1 = fp8pack4(b1.x*invb, b1.y*invb, b1.z*invb, b1.w*invb);

    g_q[(size_t)r * 64 + lane]                    = qa0;
    g_q[(size_t)r * 64 + lane + 32]               = qa1;
    g_q[(size_t)(r + BATCH) * 64 + lane]          = qb0;
    g_q[(size_t)(r + BATCH) * 64 + lane + 32]     = qb1;

    float fda = fp8_sq4(qa0) + fp8_sq4(qa1);
    float fdb = fp8_sq4(qb0) + fp8_sq4(qb1);
    #pragma unroll
    for (int o = 16; o > 0; o >>= 1) {
        fda += __shfl_xor_sync(0xFFFFFFFFu, fda, o);
        fdb += __shfl_xor_sync(0xFFFFFFFFu, fdb, o);
    }
    if (lane == 0) {
        float pos = C2 * ab * rsqrtf(na * nb);
        g_pos[r] = pos;
        g_pos[r + BATCH] = pos;
        g_diag[r]         = fda;
        g_diag[r + BATCH] = fdb;
    }
}

// ---------------------------------------------------------------------------
// k_main helpers
// ---------------------------------------------------------------------------
__device__ __forceinline__ void prefetch_b(int ct_next, uint32_t bdst, int t)
{
    const char* gb = (const char*)g_q + (size_t)ct_next * BN * 256;
    #pragma unroll
    for (int it = 0; it < 4; ++it) {
        int idx = t + it * 256;
        int row = idx >> 4, ck = idx & 15;
        cp16(bdst + row * PITCH + ck * 16, gb + row * 256 + ck * 16);
    }
    cp_commit();
}

// MODE: 0 = no interleaved epilogue, 1 = plain dual epi, 2 = masked dual epi
template <int MODE>
__device__ __forceinline__ void mma_tile(
    uint32_t bbase, uint32_t a_addr0, uint32_t a_addr1,
    uint32_t b_off0, uint32_t b_off1,
    float* accC, const float* accP, float* s_row, float* cp,
    int irBase, int cbP, int lane)
{
    #pragma unroll
    for (int e = 0; e < 32; ++e) accC[e] = 0.f;
    #pragma unroll
    for (int ks = 0; ks < 8; ++ks) {
        uint32_t af0[4], af1[4], bf0[4], bf1[4];
        ldmx4(af0, a_addr0 + ks * 32);
        ldmx4(af1, a_addr1 + ks * 32);
        ldmx4(bf0, bbase + b_off0 + ks * 32);
        ldmx4(bf1, bbase + b_off1 + ks * 32);
        mma_fp8(accC + 0,  af0, bf0[0], bf0[1]);
        mma_fp8(accC + 4,  af0, bf0[2], bf0[3]);
        mma_fp8(accC + 8,  af0, bf1[0], bf1[1]);
        mma_fp8(accC + 12, af0, bf1[2], bf1[3]);
        mma_fp8(accC + 16, af1, bf0[0], bf0[1]);
        mma_fp8(accC + 20, af1, bf0[2], bf0[3]);
        mma_fp8(accC + 24, af1, bf1[0], bf1[1]);
        mma_fp8(accC + 28, af1, bf1[2], bf1[3]);
        if (MODE == 1) {
            #pragma unroll
            for (int j = 0; j < 4; ++j) {
                const int L = ks * 4 + j;
                float e = ex2f(accP[L]);
                s_row[(L >> 4) * 2 + ((L & 3) >> 1)] += e;
                cp[((L >> 2) & 3) * 2 + (L & 1)] += e;
            }
        } else if (MODE == 2) {
            #pragma unroll
            for (int j = 0; j < 4; ++j) {
                const int L = ks * 4 + j;
                int ir = irBase + (L >> 4) * 16 + ((L & 3) >> 1) * 8;
                int jc = cbP + ((L >> 2) & 3) * 8 + (lane & 3) * 2 + (L & 1);
                float e = ex2f(accP[L]);
                if (jc >= ir) s_row[(L >> 4) * 2 + ((L & 3) >> 1)] += e;
                if (jc >  ir) cp[((L >> 2) & 3) * 2 + (L & 1)] += e;
            }
        }
    }
}

__device__ __forceinline__ void col_flush(float* cp, int cbw, int lane)
{
    #pragma unroll
    for (int b = 0; b < 8; ++b) {
        cp[b] += __shfl_xor_sync(0xFFFFFFFFu, cp[b], 4);
        cp[b] += __shfl_xor_sync(0xFFFFFFFFu, cp[b], 8);
        cp[b] += __shfl_xor_sync(0xFFFFFFFFu, cp[b], 16);
    }
    if (lane < 4) {
        #pragma unroll
        for (int b = 0; b < 8; ++b)
            atomicAdd(&g_s[cbw + (b >> 1) * 8 + lane * 2 + (b & 1)], cp[b]);
    }
}

__device__ __forceinline__ void epi_dual(const float* acc, float* s_row,
                                         int cbw, int lane)
{
    float cp[8];
    #pragma unroll
    for (int b = 0; b < 8; ++b) cp[b] = 0.f;
    #pragma unroll
    for (int L = 0; L < 32; ++L) {
        float e = ex2f(acc[L]);
        s_row[(L >> 4) * 2 + ((L & 3) >> 1)] += e;
        cp[((L >> 2) & 3) * 2 + (L & 1)] += e;
    }
    col_flush(cp, cbw, lane);
}

__device__ __forceinline__ void epi_masked(const float* acc, float* s_row,
                                           int irBase, int cbw, int lane)
{
    float cp[8];
    #pragma unroll
    for (int b = 0; b < 8; ++b) cp[b] = 0.f;
    #pragma unroll
    for (int L = 0; L < 32; ++L) {
        int ir = irBase + (L >> 4) * 16 + ((L & 3) >> 1) * 8;
        int jc = cbw + ((L >> 2) & 3) * 8 + (lane & 3) * 2 + (L & 1);
        float e = ex2f(acc[L]);
        if (jc >= ir) s_row[(L >> 4) * 2 + ((L & 3) >> 1)] += e;
        if (jc >  ir) cp[((L >> 2) & 3) * 2 + (L & 1)] += e;
    }
    col_flush(cp, cbw, lane);
}

// ---------------------------------------------------------------------------
// Kernel 2: persistent TRIANGULAR fp8 MMA, fully pipelined dual epilogue
// (masked tiles included), with fused final loss reduction (last-CTA).
// ---------------------------------------------------------------------------
__global__ __launch_bounds__(256, 2) void k_main(float* __restrict__ out)
{
    extern __shared__ char sm[];
    const uint32_t sb = smem_u32(sm);
    const int t = threadIdx.x, lane = t & 31, wid = t >> 5;
    const int wr = wid >> 1, wc = wid & 1;
    const int c = blockIdx.x;

    const int t0 = (int)(((long long)c * TT2) / GRID);
    const int t1 = (int)(((long long)(c + 1) * TT2) / GRID);

    const uint32_t a_addr0 = sb + SMEM_A
        + (uint32_t)((wr * 32 + (lane & 15)) * PITCH) + (uint32_t)((lane >> 4) * 16);
    const uint32_t a_addr1 = a_addr0 + 16 * PITCH;
    const int nsub = ((lane >> 4) << 3) + (lane & 7);
    const uint32_t bko = (uint32_t)(((lane >> 3) & 1) * 16);
    const uint32_t b_off0 = (uint32_t)((wc * 32 + nsub) * PITCH) + bko;
    const uint32_t b_off1 = (uint32_t)((wc * 32 + 16 + nsub) * PITCH) + bko;

    int job = t0;
    while (job < t1) {
        int i = (int)((129.0f - sqrtf(16641.0f - 4.0f * (float)job)) * 0.5f);
        i = max(0, min(63, i));
        while (i < 63 && (i + 1) * (129 - (i + 1)) <= job) ++i;
        while (i > 0 && i * (129 - i) > job) --i;
        const int sbase = i * (129 - i);
        const int jend = min(t1, sbase + (128 - 2 * i));
        const int rb = i * BM;
        const int off = job - sbase;
        const int irBase = rb + wr * 32 + (lane >> 2);

        #define CT(m)    (2 * i + off + (m))
        #define BB(m)    (sb + (((m) & 1) ? SMEM_B1 : SMEM_B0))
        #define CBWm(m)  (CT(m) * BN + wc * 32)
        #define MK(m)    ((off + (m)) < 2)

        // segment preamble: A stripe + tile 0 into B0
        {
            const char* ga = (const char*)g_q + (size_t)rb * 256;
            #pragma unroll
            for (int it = 0; it < 8; ++it) {
                int idx = t + it * 256;
                int row = idx >> 4, ck = idx & 15;
                cp16(sb + SMEM_A + row * PITCH + ck * 16, ga + row * 256 + ck * 16);
            }
            prefetch_b(CT(0), sb + SMEM_B0, t);
            cp_wait0(); __syncthreads();
        }

        float s_row[4] = {0.f, 0.f, 0.f, 0.f};
        float acc0[32], acc1[32];
        float cp[8];
        const int n = jend - job;

        // fill: tile 0 (no previous epilogue)
        if (n > 1) prefetch_b(CT(1), BB(1), t);
        mma_tile<0>(BB(0), a_addr0, a_addr1, b_off0, b_off1,
                    acc0, acc1, s_row, cp, irBase, 0, lane);
        if (n > 1) { cp_wait0(); __syncthreads(); }

        // m = 1 (prev tile 0 may be masked)
        if (n > 1) {
            #pragma unroll
            for (int b = 0; b < 8; ++b) cp[b] = 0.f;
            if (n > 2) prefetch_b(CT(2), BB(2), t);
            if (MK(0))
                mma_tile<2>(BB(1), a_addr0, a_addr1, b_off0, b_off1,
                            acc1, acc0, s_row, cp, irBase, CBWm(0), lane);
            else
                mma_tile<1>(BB(1), a_addr0, a_addr1, b_off0, b_off1,
                            acc1, acc0, s_row, cp, irBase, CBWm(0), lane);
            col_flush(cp, CBWm(0), lane);
            if (n > 2) { cp_wait0(); __syncthreads(); }
        }

        // m = 2 (prev tile 1 may be masked)
        if (n > 2) {
            #pragma unroll
            for (int b = 0; b < 8; ++b) cp[b] = 0.f;
            if (n > 3) prefetch_b(CT(3), BB(3), t);
            if (MK(1))
                mma_tile<2>(BB(2), a_addr0, a_addr1, b_off0, b_off1,
                            acc0, acc1, s_row, cp, irBase, CBWm(1), lane);
            else
                mma_tile<1>(BB(2), a_addr0, a_addr1, b_off0, b_off1,
                            acc0, acc1, s_row, cp, irBase, CBWm(1), lane);
            col_flush(cp, CBWm(1), lane);
            if (n > 3) { cp_wait0(); __syncthreads(); }
        }

        // steady 2x-unrolled pipeline from m = 3 (prev always unmasked)
        int m = 3;
        for (; m + 1 < n; m += 2) {
            #pragma unroll
            for (int b = 0; b < 8; ++b) cp[b] = 0.f;
            prefetch_b(CT(m + 1), BB(m + 1), t);
            mma_tile<1>(BB(m), a_addr0, a_addr1, b_off0, b_off1,
                        acc1, acc0, s_row, cp, irBase, CBWm(m - 1), lane);
            col_flush(cp, CBWm(m - 1), lane);
            cp_wait0(); __syncthreads();

            #pragma unroll
            for (int b = 0; b < 8; ++b) cp[b] = 0.f;
            if (m + 2 < n) prefetch_b(CT(m + 2), BB(m + 2), t);
            mma_tile<1>(BB(m + 1), a_addr0, a_addr1, b_off0, b_off1,
                        acc0, acc1, s_row, cp, irBase, CBWm(m), lane);
            col_flush(cp, CBWm(m), lane);
            if (m + 2 < n) { cp_wait0(); __syncthreads(); }
        }
        if (m < n) {   // leftover odd tile (m = n-1 >= 3): prev unmasked
            #pragma unroll
            for (int b = 0; b < 8; ++b) cp[b] = 0.f;
            mma_tile<1>(BB(m), a_addr0, a_addr1, b_off0, b_off1,
                        acc1, acc0, s_row, cp, irBase, CBWm(m - 1), lane);
            col_flush(cp, CBWm(m - 1), lane);
            epi_dual(acc1, s_row, CBWm(m), lane);
        } else {       // drain last tile (index n-1)
            const int last = n - 1;
            float* accL = (last & 1) ? acc1 : acc0;
            if (MK(last)) epi_masked(accL, s_row, irBase, CBWm(last), lane);
            else          epi_dual(accL, s_row, CBWm(last), lane);
        }
        #undef CT
        #undef BB
        #undef CBWm
        #undef MK

        // row flush: 4 lanes share each row
        #pragma unroll
        for (int ri = 0; ri < 4; ++ri) {
            float sv = s_row[ri];
            sv += __shfl_xor_sync(0xFFFFFFFFu, sv, 1);
            sv += __shfl_xor_sync(0xFFFFFFFFu, sv, 2);
            if ((lane & 3) == 0) {
                int r = rb + wr * 32 + (ri >> 1) * 16 + (ri & 1) * 8 + (lane >> 2);
                atomicAdd(&g_s[r], sv);
            }
        }
        __syncthreads();    // protect smem reuse by next segment
        job = jend;
    }

    // ---- fused final reduction: last CTA computes the mean loss ----
    __shared__ unsigned rankS;
    __threadfence();
    __syncthreads();
    if (t == 0) rankS = atomicAdd(&g_cnt, 1u);
    __syncthreads();
    if (rankS == GRID - 1) {
        float acc = 0.f;
        #pragma unroll 4
        for (int r = t; r < NROWS; r += 256) {
            float S = ldcg(&g_s[r]) - ex2f(g_diag[r]);
            acc += lg2f(S) - g_pos[r];
        }
        #pragma unroll
        for (int o = 16; o > 0; o >>= 1)
            acc += __shfl_xor_sync(0xFFFFFFFFu, acc, o);
        __shared__ float red[8];
        if ((t & 31) == 0) red[t >> 5] = acc;
        __syncthreads();
        if (t < 8) {
            float v = red[t];
            #pragma unroll
            for (int o = 4; o > 0; o >>= 1)
                v += __shfl_xor_sync(0xFFu, v, o);
            if (t == 0) out[0] = v * (LN2f / (float)NROWS);
        }
    }
}

// ---------------------------------------------------------------------------
extern "C" void kernel_launch(void* const* d_in, const int* in_sizes, int n_in,
                              void* d_out, int out_size)
{
    const float* ei = (const float*)d_in[0];
    const float* ej = (const float*)d_in[1];
    float* out = (float*)d_out;
    (void)in_sizes; (void)n_in; (void)out_size;

    cudaFuncSetAttribute(k_main, cudaFuncAttributeMaxDynamicSharedMemorySize,
                         SMEM_TOTAL);

    k_prep<<<BATCH / 8, 256>>>(ei, ej);
    k_main<<<GRID, 256, SMEM_TOTAL>>>(out);
}

// round 17
// speedup vs baseline: 1.0200x; 1.0200x over previous
#include <cuda_runtime.h>
#include <cstdint>
#include <math.h>

// ---------------------------------------------------------------- constants
#define BATCH 4096
#define NROWS 8192
#define DIM   256

#define LN2f  0.69314718055994531f
#define C2    2.8853900817779268f            // 2*log2(e)  (1/T * log2 e, T=0.5)
#define SCALE 1.6986442f                     // sqrt(2*log2 e)

#define BM 128                                // rows per stripe
#define BN 64                                 // cols per tile job
#define TT2     4160                          // triangle jobs: sum_i (128-2i)
#define GRID    296                           // 2 CTAs per SM, exactly

#define PITCH   272                           // smem row pitch (256B data + 16B pad)
#define A_BYTES (BM * PITCH)                  // 34816
#define B_BYTES (BN * PITCH)                  // 17408
#define SMEM_A  0
#define SMEM_B0 A_BYTES
#define SMEM_B1 (A_BYTES + B_BYTES)
#define SMEM_TOTAL (A_BYTES + 2 * B_BYTES)    // 69632 -> 2 CTAs/SM

// ------------------------------------------------------------ device scratch
__device__ __align__(16) uint32_t g_q[NROWS * 64];   // e4m3 rows (64 u32 = 256B)
__device__ float g_s[NROWS];                         // per-row exp2 sums (atomic)
__device__ float g_diag[NROWS];                      // exact fp8 self-logit (log2)
__device__ float g_pos[NROWS];                       // fp32 positive logit (log2)
__device__ unsigned g_cnt;

// ------------------------------------------------------------- asm helpers
__device__ __forceinline__ uint32_t smem_u32(const void* p) {
    uint32_t a;
    asm("{ .reg .u64 t; cvta.to.shared.u64 t, %1; cvt.u32.u64 %0, t; }" : "=r"(a) : "l"(p));
    return a;
}
__device__ __forceinline__ float ex2f(float x) {
    float y; asm("ex2.approx.ftz.f32 %0, %1;" : "=f"(y) : "f"(x)); return y;
}
__device__ __forceinline__ float lg2f(float x) {
    float y; asm("lg2.approx.f32 %0, %1;" : "=f"(y) : "f"(x)); return y;
}
__device__ __forceinline__ float ldcg(const float* p) {
    float v; asm volatile("ld.global.cg.f32 %0, [%1];" : "=f"(v) : "l"(p)); return v;
}
__device__ __forceinline__ void cp16(uint32_t s, const void* g) {
    asm volatile("cp.async.cg.shared.global [%0], [%1], 16;" :: "r"(s), "l"(g));
}
__device__ __forceinline__ void cp_commit() { asm volatile("cp.async.commit_group;"); }
__device__ __forceinline__ void cp_wait0()  { asm volatile("cp.async.wait_group 0;" ::: "memory"); }
__device__ __forceinline__ void ldmx4(uint32_t* r, uint32_t addr) {
    asm volatile("ldmatrix.sync.aligned.m8n8.x4.shared.b16 {%0,%1,%2,%3}, [%4];"
                 : "=r"(r[0]), "=r"(r[1]), "=r"(r[2]), "=r"(r[3]) : "r"(addr));
}
__device__ __forceinline__ void mma_fp8(float* c, const uint32_t* a,
                                        uint32_t b0, uint32_t b1) {
    asm volatile("mma.sync.aligned.m16n8k32.row.col.f32.e4m3.e4m3.f32 "
                 "{%0,%1,%2,%3}, {%4,%5,%6,%7}, {%8,%9}, {%0,%1,%2,%3};"
                 : "+f"(c[0]), "+f"(c[1]), "+f"(c[2]), "+f"(c[3])
                 : "r"(a[0]), "r"(a[1]), "r"(a[2]), "r"(a[3]), "r"(b0), "r"(b1));
}
__device__ __forceinline__ uint32_t fp8pack4(float x, float y, float z, float w) {
    uint16_t lo, hi; uint32_t r;
    asm("cvt.rn.satfinite.e4m3x2.f32 %0, %2, %1;" : "=h"(lo) : "f"(x), "f"(y));
    asm("cvt.rn.satfinite.e4m3x2.f32 %0, %2, %1;" : "=h"(hi) : "f"(z), "f"(w));
    asm("mov.b32 %0, {%1, %2};" : "=r"(r) : "h"(lo), "h"(hi));
    return r;
}
__device__ __forceinline__ float fp8_sq4(uint32_t v) {
    float f0, f1, f2, f3;
    asm("{ .reg .b16 l, h, a, b, c, d;\n\t"
        "  mov.b32 {l, h}, %4;\n\t"
        "  .reg .b32 p, q;\n\t"
        "  cvt.rn.f16x2.e4m3x2 p, l;\n\t"
        "  cvt.rn.f16x2.e4m3x2 q, h;\n\t"
        "  mov.b32 {a, b}, p;\n\t"
        "  mov.b32 {c, d}, q;\n\t"
        "  cvt.f32.f16 %0, a;\n\t"
        "  cvt.f32.f16 %1, b;\n\t"
        "  cvt.f32.f16 %2, c;\n\t"
        "  cvt.f32.f16 %3, d; }"
        : "=f"(f0), "=f"(f1), "=f"(f2), "=f"(f3) : "r"(v));
    return f0*f0 + f1*f1 + f2*f2 + f3*f3;
}

// ---------------------------------------------------------------------------
// Kernel 1 (prep): one warp per pair (r, r+B). Resets g_s / g_cnt.
// ---------------------------------------------------------------------------
__global__ __launch_bounds__(256) void k_prep(const float* __restrict__ ei,
                                              const float* __restrict__ ej)
{
    int w = threadIdx.x >> 5, lane = threadIdx.x & 31;
    int r = blockIdx.x * 8 + w;

    int gid = blockIdx.x * 256 + threadIdx.x;
    if (gid < NROWS) g_s[gid] = 0.f;
    if (gid == 0) g_cnt = 0;

    const float4* A4 = (const float4*)(ei + (size_t)r * DIM);
    const float4* B4 = (const float4*)(ej + (size_t)r * DIM);
    float4 a0 = A4[lane], a1 = A4[lane + 32];
    float4 b0 = B4[lane], b1 = B4[lane + 32];

    float na = a0.x*a0.x + a0.y*a0.y + a0.z*a0.z + a0.w*a0.w
             + a1.x*a1.x + a1.y*a1.y + a1.z*a1.z + a1.w*a1.w;
    float nb = b0.x*b0.x + b0.y*b0.y + b0.z*b0.z + b0.w*b0.w
             + b1.x*b1.x + b1.y*b1.y + b1.z*b1.z + b1.w*b1.w;
    float ab = a0.x*b0.x + a0.y*b0.y + a0.z*b0.z + a0.w*b0.w
             + a1.x*b1.x + a1.y*b1.y + a1.z*b1.z + a1.w*b1.w;
    #pragma unroll
    for (int o = 16; o > 0; o >>= 1) {
        na += __shfl_xor_sync(0xFFFFFFFFu, na, o);
        nb += __shfl_xor_sync(0xFFFFFFFFu, nb, o);
        ab += __shfl_xor_sync(0xFFFFFFFFu, ab, o);
    }
    float inva = rsqrtf(na) * SCALE;
    float invb = rsqrtf(nb) * SCALE;

    uint32_t qa0 = fp8pack4(a0.x*inva, a0.y*inva, a0.z*inva, a0.w*inva);
    uint32_t qa1 = fp8pack4(a1.x*inva, a1.y*inva, a1.z*inva, a1.w*inva);
    uint32_t qb0 = fp8pack4(b0.x*invb, b0.y*invb, b0.z*invb, b0.w*invb);
    uint32_t qb1 = fp8pack4(b1.x*invb, b1.y*invb, b1.z*invb, b1.w*invb);

    g_q[(size_t)r * 64 + lane]                    = qa0;
    g_q[(size_t)r * 64 + lane + 32]               = qa1;
    g_q[(size_t)(r + BATCH) * 64 + lane]          = qb0;
    g_q[(size_t)(r + BATCH) * 64 + lane + 32]     = qb1;

    float fda = fp8_sq4(qa0) + fp8_sq4(qa1);
    float fdb = fp8_sq4(qb0) + fp8_sq4(qb1);
    #pragma unroll
    for (int o = 16; o > 0; o >>= 1) {
        fda += __shfl_xor_sync(0xFFFFFFFFu, fda, o);
        fdb += __shfl_xor_sync(0xFFFFFFFFu, fdb, o);
    }
    if (lane == 0) {
        float pos = C2 * ab * rsqrtf(na * nb);
        g_pos[r] = pos;
        g_pos[r + BATCH] = pos;
        g_diag[r]         = fda;
        g_diag[r + BATCH] = fdb;
    }
}

// ---------------------------------------------------------------------------
// helpers for k_main (exact R15 structure)
// ---------------------------------------------------------------------------
__device__ __forceinline__ void prefetch_b(int ct_next, uint32_t bdst, int t)
{
    const char* gb = (const char*)g_q + (size_t)ct_next * BN * 256;
    #pragma unroll
    for (int it = 0; it < 4; ++it) {
        int idx = t + it * 256;
        int row = idx >> 4, ck = idx & 15;
        cp16(bdst + row * PITCH + ck * 16, gb + row * 256 + ck * 16);
    }
    cp_commit();
}

// MMA over one 128x64 tile; if PEND, interleave prev tile's exp2 accumulation
template <bool PEND>
__device__ __forceinline__ void mma_tile(
    uint32_t bbase, uint32_t a_addr0, uint32_t a_addr1,
    uint32_t b_off0, uint32_t b_off1,
    float* accC, const float* accP, float* s_row, float* cp)
{
    #pragma unroll
    for (int e = 0; e < 32; ++e) accC[e] = 0.f;
    #pragma unroll
    for (int ks = 0; ks < 8; ++ks) {
        uint32_t af0[4], af1[4], bf0[4], bf1[4];
        ldmx4(af0, a_addr0 + ks * 32);
        ldmx4(af1, a_addr1 + ks * 32);
        ldmx4(bf0, bbase + b_off0 + ks * 32);
        ldmx4(bf1, bbase + b_off1 + ks * 32);
        mma_fp8(accC + 0,  af0, bf0[0], bf0[1]);
        mma_fp8(accC + 4,  af0, bf0[2], bf0[3]);
        mma_fp8(accC + 8,  af0, bf1[0], bf1[1]);
        mma_fp8(accC + 12, af0, bf1[2], bf1[3]);
        mma_fp8(accC + 16, af1, bf0[0], bf0[1]);
        mma_fp8(accC + 20, af1, bf0[2], bf0[3]);
        mma_fp8(accC + 24, af1, bf1[0], bf1[1]);
        mma_fp8(accC + 28, af1, bf1[2], bf1[3]);
        if (PEND) {
            #pragma unroll
            for (int j = 0; j < 4; ++j) {
                const int L = ks * 4 + j;
                float e = ex2f(accP[L]);
                s_row[(L >> 4) * 2 + ((L & 3) >> 1)] += e;
                cp[((L >> 2) & 3) * 2 + (L & 1)] += e;
            }
        }
    }
}

__device__ __forceinline__ void col_flush(float* cp, int cbw, int lane)
{
    #pragma unroll
    for (int b = 0; b < 8; ++b) {
        cp[b] += __shfl_xor_sync(0xFFFFFFFFu, cp[b], 4);
        cp[b] += __shfl_xor_sync(0xFFFFFFFFu, cp[b], 8);
        cp[b] += __shfl_xor_sync(0xFFFFFFFFu, cp[b], 16);
    }
    if (lane < 4) {
        #pragma unroll
        for (int b = 0; b < 8; ++b)
            atomicAdd(&g_s[cbw + (b >> 1) * 8 + lane * 2 + (b & 1)], cp[b]);
    }
}

__device__ __forceinline__ void epi_dual(const float* acc, float* s_row,
                                         int cbw, int lane)
{
    float cp[8];
    #pragma unroll
    for (int b = 0; b < 8; ++b) cp[b] = 0.f;
    #pragma unroll
    for (int L = 0; L < 32; ++L) {
        float e = ex2f(acc[L]);
        s_row[(L >> 4) * 2 + ((L & 3) >> 1)] += e;
        cp[((L >> 2) & 3) * 2 + (L & 1)] += e;
    }
    col_flush(cp, cbw, lane);
}

__device__ __forceinline__ void epi_masked(const float* acc, float* s_row,
                                           int rb, int wr, int cbw, int lane)
{
    float cp[8];
    #pragma unroll
    for (int b = 0; b < 8; ++b) cp[b] = 0.f;
    #pragma unroll
    for (int L = 0; L < 32; ++L) {
        int ir = rb + wr * 32 + (L >> 4) * 16 + ((L & 3) >> 1) * 8 + (lane >> 2);
        int jc = cbw + ((L >> 2) & 3) * 8 + (lane & 3) * 2 + (L & 1);
        float e = ex2f(acc[L]);
        if (jc >= ir) s_row[(L >> 4) * 2 + ((L & 3) >> 1)] += e;
        if (jc >  ir) cp[((L >> 2) & 3) * 2 + (L & 1)] += e;
    }
    col_flush(cp, cbw, lane);
}

// ---------------------------------------------------------------------------
// Kernel 2: persistent TRIANGULAR fp8 MMA with deferred dual epilogue
// (R15 structure) + fused last-CTA final loss reduction.
// ---------------------------------------------------------------------------
__global__ __launch_bounds__(256, 2) void k_main(float* __restrict__ out)
{
    extern __shared__ char sm[];
    const uint32_t sb = smem_u32(sm);
    const int t = threadIdx.x, lane = t & 31, wid = t >> 5;
    const int wr = wid >> 1, wc = wid & 1;
    const int c = blockIdx.x;

    const int t0 = (int)(((long long)c * TT2) / GRID);
    const int t1 = (int)(((long long)(c + 1) * TT2) / GRID);

    const uint32_t a_addr0 = sb + SMEM_A
        + (uint32_t)((wr * 32 + (lane & 15)) * PITCH) + (uint32_t)((lane >> 4) * 16);
    const uint32_t a_addr1 = a_addr0 + 16 * PITCH;
    const int nsub = ((lane >> 4) << 3) + (lane & 7);
    const uint32_t bko = (uint32_t)(((lane >> 3) & 1) * 16);
    const uint32_t b_off0 = (uint32_t)((wc * 32 + nsub) * PITCH) + bko;
    const uint32_t b_off1 = (uint32_t)((wc * 32 + 16 + nsub) * PITCH) + bko;

    int job = t0;
    while (job < t1) {
        int i = (int)((129.0f - sqrtf(16641.0f - 4.0f * (float)job)) * 0.5f);
        i = max(0, min(63, i));
        while (i < 63 && (i + 1) * (129 - (i + 1)) <= job) ++i;
        while (i > 0 && i * (129 - i) > job) --i;
        const int sbase = i * (129 - i);
        const int jend = min(t1, sbase + (128 - 2 * i));
        const int rb = i * BM;

        // load A stripe + first B tile
        {
            const char* ga = (const char*)g_q + (size_t)rb * 256;
            #pragma unroll
            for (int it = 0; it < 8; ++it) {
                int idx = t + it * 256;
                int row = idx >> 4, ck = idx & 15;
                cp16(sb + SMEM_A + row * PITCH + ck * 16, ga + row * 256 + ck * 16);
            }
            prefetch_b(2 * i + (job - sbase), sb + SMEM_B0, t);
            cp_wait0(); __syncthreads();
        }

        float s_row[4] = {0.f, 0.f, 0.f, 0.f};
        float acc0[32], acc1[32];
        float cp[8];

        int jj = job;

        // ---- masked prologue tiles (at most 2, only at stripe start) ----
        while (jj < jend && (jj - sbase) < 2) {
            const int ct = 2 * i + (jj - sbase);
            const uint32_t bbase = sb + (((jj - job) & 1) ? SMEM_B1 : SMEM_B0);
            const bool pf = (jj + 1 < jend);
            if (pf)
                prefetch_b(ct + 1, sb + (((jj + 1 - job) & 1) ? SMEM_B1 : SMEM_B0), t);
            mma_tile<false>(bbase, a_addr0, a_addr1, b_off0, b_off1,
                            acc0, acc1, s_row, cp);
            epi_masked(acc0, s_row, rb, wr, ct * BN + wc * 32, lane);
            if (pf) { cp_wait0(); __syncthreads(); }
            ++jj;
        }

        // ---- pipelined unmasked tiles ----
        const int n = jend - jj;
        if (n > 0) {
            #define CTm(m)   (2 * i + ((jj + (m)) - sbase))
            #define BBASE(m) (sb + ((((jj + (m)) - job) & 1) ? SMEM_B1 : SMEM_B0))
            #define CBW(m)   (CTm(m) * BN + wc * 32)
            #define PF(m)    ((jj + (m) + 1) < jend)

            // fill: tile 0
            if (PF(0)) prefetch_b(CTm(0) + 1, BBASE(1), t);
            mma_tile<false>(BBASE(0), a_addr0, a_addr1, b_off0, b_off1,
                            acc0, acc1, s_row, cp);
            if (PF(0)) { cp_wait0(); __syncthreads(); }

            int k = 1;
            for (; k + 1 < n; k += 2) {
                #pragma unroll
                for (int b = 0; b < 8; ++b) cp[b] = 0.f;
                if (PF(k)) prefetch_b(CTm(k) + 1, BBASE(k + 1), t);
                mma_tile<true>(BBASE(k), a_addr0, a_addr1, b_off0, b_off1,
                               acc1, acc0, s_row, cp);
                col_flush(cp, CBW(k - 1), lane);
                if (PF(k)) { cp_wait0(); __syncthreads(); }

                #pragma unroll
                for (int b = 0; b < 8; ++b) cp[b] = 0.f;
                if (PF(k + 1)) prefetch_b(CTm(k + 1) + 1, BBASE(k + 2), t);
                mma_tile<true>(BBASE(k + 1), a_addr0, a_addr1, b_off0, b_off1,
                               acc0, acc1, s_row, cp);
                col_flush(cp, CBW(k), lane);
                if (PF(k + 1)) { cp_wait0(); __syncthreads(); }
            }
            if (k < n) {
                #pragma unroll
                for (int b = 0; b < 8; ++b) cp[b] = 0.f;
                if (PF(k)) prefetch_b(CTm(k) + 1, BBASE(k + 1), t);
                mma_tile<true>(BBASE(k), a_addr0, a_addr1, b_off0, b_off1,
                               acc1, acc0, s_row, cp);
                col_flush(cp, CBW(k - 1), lane);
                if (PF(k)) { cp_wait0(); __syncthreads(); }
                epi_dual(acc1, s_row, CBW(k), lane);
            } else {
                epi_dual(acc0, s_row, CBW(n - 1), lane);
            }
            #undef CTm
            #undef BBASE
            #undef CBW
            #undef PF
        }

        // row flush: 4 lanes share each row
        #pragma unroll
        for (int ri = 0; ri < 4; ++ri) {
            float sv = s_row[ri];
            sv += __shfl_xor_sync(0xFFFFFFFFu, sv, 1);
            sv += __shfl_xor_sync(0xFFFFFFFFu, sv, 2);
            if ((lane & 3) == 0) {
                int r = rb + wr * 32 + (ri >> 1) * 16 + (ri & 1) * 8 + (lane >> 2);
                atomicAdd(&g_s[r], sv);
            }
        }
        __syncthreads();    // protect smem reuse by next stripe
        job = jend;
    }

    // ---- fused final reduction: last CTA computes the mean loss ----
    __shared__ unsigned rankS;
    __threadfence();
    __syncthreads();
    if (t == 0) rankS = atomicAdd(&g_cnt, 1u);
    __syncthreads();
    if (rankS == GRID - 1) {
        float acc = 0.f;
        #pragma unroll 4
        for (int r = t; r < NROWS; r += 256) {
            float S = ldcg(&g_s[r]) - ex2f(g_diag[r]);
            acc += lg2f(S) - g_pos[r];
        }
        #pragma unroll
        for (int o = 16; o > 0; o >>= 1)
            acc += __shfl_xor_sync(0xFFFFFFFFu, acc, o);
        __shared__ float red[8];
        if ((t & 31) == 0) red[t >> 5] = acc;
        __syncthreads();
        if (t < 8) {
            float v = red[t];
            #pragma unroll
            for (int o = 4; o > 0; o >>= 1)
                v += __shfl_xor_sync(0xFFu, v, o);
            if (t == 0) out[0] = v * (LN2f / (float)NROWS);
        }
    }
}

// ---------------------------------------------------------------------------
extern "C" void kernel_launch(void* const* d_in, const int* in_sizes, int n_in,
                              void* d_out, int out_size)
{
    const float* ei = (const float*)d_in[0];
    const float* ej = (const float*)d_in[1];
    float* out = (float*)d_out;
    (void)in_sizes; (void)n_in; (void)out_size;

    cudaFuncSetAttribute(k_main, cudaFuncAttributeMaxDynamicSharedMemorySize,
                         SMEM_TOTAL);

    k_prep<<<BATCH / 8, 256>>>(ei, ej);
    k_main<<<GRID, 256, SMEM_TOTAL>>>(out);
}